// round 6
// baseline (speedup 1.0000x reference)
#include <cuda_runtime.h>
#include <cstdint>

#define DIM 256
#define OUT 8
#define TPG 64            // tokens per warp-group (2 per lane)
#define WARPS 4           // warps per block (128 threads)

__device__ __forceinline__ unsigned long long pk2(float lo, float hi) {
    unsigned long long r;
    asm("mov.b64 %0, {%1,%2};" : "=l"(r) : "f"(lo), "f"(hi));
    return r;
}
__device__ __forceinline__ unsigned long long fma2(unsigned long long a, unsigned long long b,
                                                   unsigned long long c) {
    unsigned long long d;
    asm("fma.rn.f32x2 %0, %1, %2, %3;" : "=l"(d) : "l"(a), "l"(b), "l"(c));
    return d;
}

struct EpiParams { const float *W2, *b1, *b2, *g, *bt; };

__device__ __forceinline__ void epilogue(const unsigned long long* acc, const EpiParams& ep,
                                         float* __restrict__ out, int tok)
{
    float gg[OUT];
    #pragma unroll
    for (int o = 0; o < OUT; o++) {
        float2 p = *(const float2*)&acc[o];
        float hv = p.x + p.y + ep.b1[o];
        gg[o] = 0.5f * hv * (1.0f + erff(hv * 0.70710678118654752440f));
    }
    float y[OUT];
    #pragma unroll
    for (int p = 0; p < OUT; p++) {
        float s = ep.b2[p];
        #pragma unroll
        for (int o = 0; o < OUT; o++) s = fmaf(ep.W2[p * 8 + o], gg[o], s);
        y[p] = s;
    }
    float mu = 0.0f;
    #pragma unroll
    for (int p = 0; p < OUT; p++) mu += y[p];
    mu *= 0.125f;
    float var = 0.0f;
    #pragma unroll
    for (int p = 0; p < OUT; p++) { float d = y[p] - mu; var = fmaf(d, d, var); }
    var *= 0.125f;
    float rs = rsqrtf(var + 1e-5f);

    float4 o0, o1;
    o0.x = (y[0] - mu) * rs * ep.g[0] + ep.bt[0];
    o0.y = (y[1] - mu) * rs * ep.g[1] + ep.bt[1];
    o0.z = (y[2] - mu) * rs * ep.g[2] + ep.bt[2];
    o0.w = (y[3] - mu) * rs * ep.g[3] + ep.bt[3];
    o1.x = (y[4] - mu) * rs * ep.g[4] + ep.bt[4];
    o1.y = (y[5] - mu) * rs * ep.g[5] + ep.bt[5];
    o1.z = (y[6] - mu) * rs * ep.g[6] + ep.bt[6];
    o1.w = (y[7] - mu) * rs * ep.g[7] + ep.bt[7];
    float4* op = (float4*)(out + (size_t)tok * 8);
    op[0] = o0;
    op[1] = o1;
}

__global__ __launch_bounds__(128, 5)
void ffn_kernel(const float* __restrict__ x, const float* __restrict__ W1,
                const float* __restrict__ b1, const float* __restrict__ W2,
                const float* __restrict__ b2, const float* __restrict__ gamma,
                const float* __restrict__ beta, float* __restrict__ out, int ntok)
{
    // packed W1 dim-pairs: Wp[dp*8+o] = {W1[o][2dp], W1[o][2dp+1]}  (1024 u64 = 8KB)
    __shared__ unsigned long long Wp[DIM / 2 * OUT];
    __shared__ float sW2[64], sb1[8], sb2[8], sg[8], sbt[8];

    const int tid = threadIdx.x;

    // ---- one-time init ----
    {
        #pragma unroll
        for (int q = 0; q < 8; q++) {
            int idx = tid * 8 + q;               // 128 threads x 8 = 1024
            int d = idx >> 3;
            int o = idx & 7;
            Wp[idx] = pk2(W1[o * DIM + 2 * d], W1[o * DIM + 2 * d + 1]);
        }
        if (tid < 64) sW2[tid] = W2[tid];
        if (tid < 8) { sb1[tid] = b1[tid]; sb2[tid] = b2[tid]; sg[tid] = gamma[tid]; sbt[tid] = beta[tid]; }
    }
    __syncthreads();

    const int lane = tid & 31;
    const int warp = tid >> 5;
    const int warp_global = blockIdx.x * WARPS + warp;
    const int nwarps = gridDim.x * WARPS;
    const int ngroups = (ntok + TPG - 1) / TPG;
    EpiParams ep{sW2, sb1, sb2, sg, sbt};

    const ulonglong2* Wp2 = (const ulonglong2*)Wp;      // 4 ulonglong2 per dim-pair

    for (int g = warp_global; g < ngroups; g += nwarps) {
        const int base = g * TPG;
        const int tokA = base + lane;
        const int tokB = base + 32 + lane;

        // OOB rows clamp to row 0 (harmless redundant read); epilogue is guarded.
        const ulonglong2* rA = (const ulonglong2*)(x + (size_t)(tokA < ntok ? tokA : 0) * DIM);
        const ulonglong2* rB = (const ulonglong2*)(x + (size_t)(tokB < ntok ? tokB : 0) * DIM);

        unsigned long long accA[OUT], accB[OUT];
        #pragma unroll
        for (int o = 0; o < OUT; o++) { accA[o] = 0ull; accB[o] = 0ull; }

        // 4 outer iters (not unrolled, keeps body in I$) x 4 chunks of 16 dims
        for (int q = 0; q < 4; q++) {
            #pragma unroll
            for (int cc = 0; cc < 4; cc++) {
                const int c = q * 4 + cc;                 // chunk of 16 dims
                ulonglong2 xa0 = rA[c * 4 + 0];
                ulonglong2 xa1 = rA[c * 4 + 1];
                ulonglong2 xa2 = rA[c * 4 + 2];
                ulonglong2 xa3 = rA[c * 4 + 3];
                ulonglong2 xb0 = rB[c * 4 + 0];
                ulonglong2 xb1 = rB[c * 4 + 1];
                ulonglong2 xb2 = rB[c * 4 + 2];
                ulonglong2 xb3 = rB[c * 4 + 3];

                #pragma unroll
                for (int i = 0; i < 4; i++) {
                    ulonglong2 xa = (i == 0) ? xa0 : (i == 1) ? xa1 : (i == 2) ? xa2 : xa3;
                    ulonglong2 xb = (i == 0) ? xb0 : (i == 1) ? xb1 : (i == 2) ? xb2 : xb3;
                    const ulonglong2* w = Wp2 + (size_t)(c * 8 + 2 * i) * 4;
                    ulonglong2 w0 = w[0], w1 = w[1], w2 = w[2], w3 = w[3];
                    accA[0] = fma2(xa.x, w0.x, accA[0]);  accB[0] = fma2(xb.x, w0.x, accB[0]);
                    accA[1] = fma2(xa.x, w0.y, accA[1]);  accB[1] = fma2(xb.x, w0.y, accB[1]);
                    accA[2] = fma2(xa.x, w1.x, accA[2]);  accB[2] = fma2(xb.x, w1.x, accB[2]);
                    accA[3] = fma2(xa.x, w1.y, accA[3]);  accB[3] = fma2(xb.x, w1.y, accB[3]);
                    accA[4] = fma2(xa.x, w2.x, accA[4]);  accB[4] = fma2(xb.x, w2.x, accB[4]);
                    accA[5] = fma2(xa.x, w2.y, accA[5]);  accB[5] = fma2(xb.x, w2.y, accB[5]);
                    accA[6] = fma2(xa.x, w3.x, accA[6]);  accB[6] = fma2(xb.x, w3.x, accB[6]);
                    accA[7] = fma2(xa.x, w3.y, accA[7]);  accB[7] = fma2(xb.x, w3.y, accB[7]);
                    ulonglong2 w4 = w[4], w5 = w[5], w6 = w[6], w7 = w[7];
                    accA[0] = fma2(xa.y, w4.x, accA[0]);  accB[0] = fma2(xb.y, w4.x, accB[0]);
                    accA[1] = fma2(xa.y, w4.y, accA[1]);  accB[1] = fma2(xb.y, w4.y, accB[1]);
                    accA[2] = fma2(xa.y, w5.x, accA[2]);  accB[2] = fma2(xb.y, w5.x, accB[2]);
                    accA[3] = fma2(xa.y, w5.y, accA[3]);  accB[3] = fma2(xb.y, w5.y, accB[3]);
                    accA[4] = fma2(xa.y, w6.x, accA[4]);  accB[4] = fma2(xb.y, w6.x, accB[4]);
                    accA[5] = fma2(xa.y, w6.y, accA[5]);  accB[5] = fma2(xb.y, w6.y, accB[5]);
                    accA[6] = fma2(xa.y, w7.x, accA[6]);  accB[6] = fma2(xb.y, w7.x, accB[6]);
                    accA[7] = fma2(xa.y, w7.y, accA[7]);  accB[7] = fma2(xb.y, w7.y, accB[7]);
                }
            }
        }

        if (tokA < ntok) epilogue(accA, ep, out, tokA);
        if (tokB < ntok) epilogue(accB, ep, out, tokB);
    }
}

extern "C" void kernel_launch(void* const* d_in, const int* in_sizes, int n_in,
                              void* d_out, int out_size)
{
    const float* x     = (const float*)d_in[0];
    const float* W1    = (const float*)d_in[1];
    const float* b1    = (const float*)d_in[2];
    const float* W2    = (const float*)d_in[3];
    const float* b2    = (const float*)d_in[4];
    const float* gamma = (const float*)d_in[5];
    const float* beta  = (const float*)d_in[6];
    float* out = (float*)d_out;

    int ntok = in_sizes[0] / DIM;               // 262144 for the bench shape
    int ngroups = (ntok + TPG - 1) / TPG;       // warp-groups of 64 tokens
    int blocks = (ngroups + WARPS - 1) / WARPS; // 1 group per warp at full shape
    if (blocks > 1024) blocks = 1024;
    if (blocks < 1) blocks = 1;

    ffn_kernel<<<blocks, 128>>>(x, W1, b1, W2, b2, gamma, beta, out, ntok);
}

// round 7
// speedup vs baseline: 1.6533x; 1.6533x over previous
#include <cuda_runtime.h>
#include <cstdint>

#define DIM 256
#define OUT 8
#define CHUNK 32          // dims per pipeline chunk
#define NCHUNK 8          // DIM / CHUNK
#define ROWF 32           // floats per row (no pad; XOR swizzle handles banks)
#define TPW 32            // tokens per warp group (1 per lane)
#define WARPS 8           // warps per block

#define STAGE_FLOATS (TPW * ROWF)                 // 1024
#define XBUF_FLOATS  (WARPS * 2 * STAGE_FLOATS)   // 16384
#define XBUF_BYTES   (XBUF_FLOATS * 4)            // 65536
#define WP_BYTES     (DIM / 2 * OUT * 8)          // 8192
#define SMEM_TOTAL   (XBUF_BYTES + WP_BYTES + 96 * 4)   // 74112 -> 3 blocks/SM

__device__ __forceinline__ unsigned long long pk2(float lo, float hi) {
    unsigned long long r;
    asm("mov.b64 %0, {%1,%2};" : "=l"(r) : "f"(lo), "f"(hi));
    return r;
}
__device__ __forceinline__ unsigned long long fma2(unsigned long long a, unsigned long long b,
                                                   unsigned long long c) {
    unsigned long long d;
    asm("fma.rn.f32x2 %0, %1, %2, %3;" : "=l"(d) : "l"(a), "l"(b), "l"(c));
    return d;
}
__device__ __forceinline__ void cp16(uint32_t saddr, const float* gptr) {
    asm volatile("cp.async.cg.shared.global [%0], [%1], 16;" :: "r"(saddr), "l"(gptr));
}

struct EpiParams { const float *W2, *b1, *b2, *g, *bt; };

__device__ __forceinline__ void epilogue(const unsigned long long* acc, const EpiParams& ep,
                                         float* __restrict__ out, int tok)
{
    float gg[OUT];
    #pragma unroll
    for (int o = 0; o < OUT; o++) {
        float2 p = *(const float2*)&acc[o];
        float hv = p.x + p.y + ep.b1[o];
        gg[o] = 0.5f * hv * (1.0f + erff(hv * 0.70710678118654752440f));
    }
    float y[OUT];
    #pragma unroll
    for (int p = 0; p < OUT; p++) {
        float s = ep.b2[p];
        #pragma unroll
        for (int o = 0; o < OUT; o++) s = fmaf(ep.W2[p * 8 + o], gg[o], s);
        y[p] = s;
    }
    float mu = 0.0f;
    #pragma unroll
    for (int p = 0; p < OUT; p++) mu += y[p];
    mu *= 0.125f;
    float var = 0.0f;
    #pragma unroll
    for (int p = 0; p < OUT; p++) { float d = y[p] - mu; var = fmaf(d, d, var); }
    var *= 0.125f;
    float rs = rsqrtf(var + 1e-5f);

    float4 o0, o1;
    o0.x = (y[0] - mu) * rs * ep.g[0] + ep.bt[0];
    o0.y = (y[1] - mu) * rs * ep.g[1] + ep.bt[1];
    o0.z = (y[2] - mu) * rs * ep.g[2] + ep.bt[2];
    o0.w = (y[3] - mu) * rs * ep.g[3] + ep.bt[3];
    o1.x = (y[4] - mu) * rs * ep.g[4] + ep.bt[4];
    o1.y = (y[5] - mu) * rs * ep.g[5] + ep.bt[5];
    o1.z = (y[6] - mu) * rs * ep.g[6] + ep.bt[6];
    o1.w = (y[7] - mu) * rs * ep.g[7] + ep.bt[7];
    float4* op = (float4*)(out + (size_t)tok * 8);
    op[0] = o0;
    op[1] = o1;
}

__global__ __launch_bounds__(256, 3)
void ffn_kernel(const float* __restrict__ x, const float* __restrict__ W1,
                const float* __restrict__ b1, const float* __restrict__ W2,
                const float* __restrict__ b2, const float* __restrict__ gamma,
                const float* __restrict__ beta, float* __restrict__ out, int ntok)
{
    extern __shared__ char smem_raw[];
    float* xbuf = (float*)smem_raw;
    unsigned long long* Wp = (unsigned long long*)(smem_raw + XBUF_BYTES);
    float* tail = (float*)(smem_raw + XBUF_BYTES + WP_BYTES);
    float* sW2 = tail;          // 64
    float* sb1 = tail + 64;     // 8
    float* sb2 = tail + 72;     // 8
    float* sg  = tail + 80;     // 8
    float* sbt = tail + 88;     // 8

    const int tid = threadIdx.x;

    // ---- one-time init: packed W1 dim-pairs Wp[dp*8+o] = {W1[o][2dp], W1[o][2dp+1]} ----
    {
        int e = tid * 4;
        #pragma unroll
        for (int q = 0; q < 4; q++) {
            int idx = e + q;
            int d = idx >> 3;
            int o = idx & 7;
            Wp[idx] = pk2(W1[o * DIM + 2 * d], W1[o * DIM + 2 * d + 1]);
        }
        if (tid < 64) sW2[tid] = W2[tid];
        if (tid < 8) { sb1[tid] = b1[tid]; sb2[tid] = b2[tid]; sg[tid] = gamma[tid]; sbt[tid] = beta[tid]; }
    }
    __syncthreads();

    const int lane = tid & 31;
    const int warp = tid >> 5;
    const int warp_global = blockIdx.x * WARPS + warp;
    const int nwarps = gridDim.x * WARPS;
    const int ngroups = (ntok + TPW - 1) / TPW;

    float* wtile = xbuf + warp * 2 * STAGE_FLOATS;
    const uint32_t wtile_su = (uint32_t)__cvta_generic_to_shared(wtile);
    EpiParams ep{sW2, sb1, sb2, sg, sbt};

    // staging split: lin = it*32+lane, r = lin>>3 (token row), j = lin&7 (16B piece)
    // physical piece = j ^ (r&7)  -> conflict-free on write (8 lanes of one row per phase)
    // and on read (lane reads row=lane, piece i at phys i^(lane&7); distinct per 8-lane phase)
    const int r0 = lane >> 3, j0 = lane & 7;
    const ulonglong2* Wp2 = (const ulonglong2*)Wp;

    for (int g = warp_global; g < ngroups; g += nwarps) {
        const int base = g * TPW;
        const bool full = (base + TPW) <= ntok;
        const float* xg = x + (size_t)base * DIM;

        // ---- issue chunk c into stage stg ----
        auto stage_cp = [&](int c, int stg) {
            const uint32_t sbase = wtile_su + (uint32_t)(stg * STAGE_FLOATS) * 4;
            if (full) {
                #pragma unroll
                for (int it = 0; it < 8; it++) {
                    int r = it * 4 + r0;
                    int pj = j0 ^ (r & 7);
                    cp16(sbase + (uint32_t)(r * ROWF + pj * 4) * 4,
                         xg + (size_t)r * DIM + c * CHUNK + j0 * 4);
                }
            } else {
                #pragma unroll
                for (int it = 0; it < 8; it++) {
                    int r = it * 4 + r0;
                    int pj = j0 ^ (r & 7);
                    if (base + r < ntok)
                        cp16(sbase + (uint32_t)(r * ROWF + pj * 4) * 4,
                             xg + (size_t)r * DIM + c * CHUNK + j0 * 4);
                }
            }
            asm volatile("cp.async.commit_group;");
        };

        unsigned long long acc[OUT];
        #pragma unroll
        for (int o = 0; o < OUT; o++) acc[o] = 0ull;

        const float* myrow = wtile + lane * ROWF;
        const int l7 = lane & 7;

        // ---- compute chunk c from stage stg ----
        auto compute = [&](int c, int stg) {
            const float* r = myrow + stg * STAGE_FLOATS;
            #pragma unroll
            for (int i = 0; i < 8; i++) {
                // logical piece i lives at physical piece i^l7
                ulonglong2 xv = *(const ulonglong2*)(r + ((i ^ l7) << 2));
                const int dpg = c * 16 + 2 * i;
                const ulonglong2* w = Wp2 + (size_t)dpg * 4;
                {
                    ulonglong2 w0 = w[0];
                    acc[0] = fma2(xv.x, w0.x, acc[0]);
                    acc[1] = fma2(xv.x, w0.y, acc[1]);
                    ulonglong2 w1 = w[1];
                    acc[2] = fma2(xv.x, w1.x, acc[2]);
                    acc[3] = fma2(xv.x, w1.y, acc[3]);
                    ulonglong2 w2 = w[2];
                    acc[4] = fma2(xv.x, w2.x, acc[4]);
                    acc[5] = fma2(xv.x, w2.y, acc[5]);
                    ulonglong2 w3 = w[3];
                    acc[6] = fma2(xv.x, w3.x, acc[6]);
                    acc[7] = fma2(xv.x, w3.y, acc[7]);
                }
                {
                    ulonglong2 w4 = w[4];
                    acc[0] = fma2(xv.y, w4.x, acc[0]);
                    acc[1] = fma2(xv.y, w4.y, acc[1]);
                    ulonglong2 w5 = w[5];
                    acc[2] = fma2(xv.y, w5.x, acc[2]);
                    acc[3] = fma2(xv.y, w5.y, acc[3]);
                    ulonglong2 w6 = w[6];
                    acc[4] = fma2(xv.y, w6.x, acc[4]);
                    acc[5] = fma2(xv.y, w6.y, acc[5]);
                    ulonglong2 w7 = w[7];
                    acc[6] = fma2(xv.y, w7.x, acc[6]);
                    acc[7] = fma2(xv.y, w7.y, acc[7]);
                }
            }
        };

        // ---- 2-stage pipeline (R3-proven) ----
        stage_cp(0, 0);
        #pragma unroll
        for (int c = 0; c < NCHUNK; c++) {
            if (c + 1 < NCHUNK) {
                stage_cp(c + 1, (c + 1) & 1);
                asm volatile("cp.async.wait_group 1;");
            } else {
                asm volatile("cp.async.wait_group 0;");
            }
            __syncwarp();
            compute(c, c & 1);
            __syncwarp();
        }

        // ---- epilogue: this thread owns token base+lane ----
        const int tok = base + lane;
        if (tok < ntok) epilogue(acc, ep, out, tok);
        __syncwarp();   // protect tile reuse across group iterations
    }
}

extern "C" void kernel_launch(void* const* d_in, const int* in_sizes, int n_in,
                              void* d_out, int out_size)
{
    const float* x     = (const float*)d_in[0];
    const float* W1    = (const float*)d_in[1];
    const float* b1    = (const float*)d_in[2];
    const float* W2    = (const float*)d_in[3];
    const float* b2    = (const float*)d_in[4];
    const float* gamma = (const float*)d_in[5];
    const float* beta  = (const float*)d_in[6];
    float* out = (float*)d_out;

    int ntok = in_sizes[0] / DIM;               // 262144 for the bench shape
    int ngroups = (ntok + TPW - 1) / TPW;       // warp-groups of 32 tokens
    int blocks = (ngroups + WARPS - 1) / WARPS;
    if (blocks > 1024) blocks = 1024;
    if (blocks < 1) blocks = 1;

    cudaFuncSetAttribute(ffn_kernel, cudaFuncAttributeMaxDynamicSharedMemorySize, SMEM_TOTAL);
    ffn_kernel<<<blocks, 256, SMEM_TOTAL>>>(x, W1, b1, W2, b2, gamma, beta, out, ntok);
}